// round 14
// baseline (speedup 1.0000x reference)
#include <cuda_runtime.h>
#include <cuda_bf16.h>

// VariableSelectionNetwork: B=32, S=512, F=32, H=64
//   A[f][g] = sum_h W_feat[f,h]*W_gate[f*H+h, g];  c = b_gate + sum b_feat.W_gate
//   gates = softmax(x @ A + c);  out = [g*x, g] @ [W_feat; b_feat]
// Prep: partial A/c over 4 h-quarters, 128 blocks.
// Main: 128 blocks x 512 threads, 128 rows/block (R12 structure) with:
//   - W' pre-duplicated in smem ({w,w} float2) -> no dup movs in hot loop
//   - explicit 2-stage software pipeline: k+1 loads issue before k's FFMA2s
//   Phase 2 iter: 4 LDS.128 + 16 FFMA2.

#define F_DIM 32
#define H_DIM 64
#define ROWS  16384
#define MB_ROWS 128
#define MAIN_GRID (ROWS / MB_ROWS)   // 128

typedef unsigned long long ull;

__device__ float g_Apart[4 * 1024];
__device__ float g_Cpart[4 * 1024];

// ---------------- f32x2 helpers ----------------
__device__ __forceinline__ ull pk2(float a, float b) {
    ull r;
    asm("mov.b64 %0, {%1, %2};" : "=l"(r) : "f"(a), "f"(b));
    return r;
}
__device__ __forceinline__ void ffma2(ull& d, ull a, ull b) {
    asm("fma.rn.f32x2 %0, %1, %2, %3;" : "=l"(d) : "l"(a), "l"(b), "l"(d));
}
__device__ __forceinline__ void fadd2(ull& d, ull a) {
    asm("add.rn.f32x2 %0, %1, %2;" : "=l"(d) : "l"(d), "l"(a));
}
__device__ __forceinline__ float2 unpk2(ull v) {
    float2 r;
    asm("mov.b64 {%0, %1}, %2;" : "=f"(r.x), "=f"(r.y) : "l"(v));
    return r;
}

// ---------------------------------------------------------------------------
// Prep: 128 blocks (f = bid>>2, h-quarter q = bid&3), 128 threads.
// ---------------------------------------------------------------------------
__global__ void __launch_bounds__(128) vsn_prep_kernel(
    const float* __restrict__ W_feat,
    const float* __restrict__ b_feat,
    const float* __restrict__ W_gate)
{
    const int f  = blockIdx.x >> 2;
    const int q  = blockIdx.x & 3;
    const int g  = threadIdx.x & 31;
    const int hh = threadIdx.x >> 5;

    float a = 0.f, c = 0.f;
#pragma unroll
    for (int kk = 0; kk < 4; kk++) {
        const int h = q * 16 + hh * 4 + kk;
        const float wg = W_gate[(f * H_DIM + h) * F_DIM + g];
        a = fmaf(W_feat[f * H_DIM + h], wg, a);
        c = fmaf(b_feat[f * H_DIM + h], wg, c);
    }

    __shared__ float rA[4][32];
    __shared__ float rC[4][32];
    rA[hh][g] = a;
    rC[hh][g] = c;
    __syncthreads();

    if (threadIdx.x < 32) {
        float as = 0.f, cs = 0.f;
#pragma unroll
        for (int r = 0; r < 4; r++) { as += rA[r][threadIdx.x]; cs += rC[r][threadIdx.x]; }
        g_Apart[q * 1024 + f * F_DIM + threadIdx.x] = as;
        g_Cpart[q * 1024 + f * F_DIM + threadIdx.x] = cs;
    }
}

// ---------------------------------------------------------------------------
// Main kernel: 128 blocks x 512 threads, 128 rows/block. Dynamic smem 68 KB:
//   sWBd [64][64] float2-dup (32 KB), sX [64][128] (32 KB; reused as splitk
//   buffer), sA [32][32] (4 KB).
// ---------------------------------------------------------------------------
__global__ void __launch_bounds__(512, 1) vsn_main_kernel(
    const float* __restrict__ features,
    const float* __restrict__ b_gate,
    const float* __restrict__ W_feat,
    const float* __restrict__ b_feat,
    float* __restrict__ out)
{
    extern __shared__ float dyn[];
    float2* sWBd = (float2*)dyn;           // 4096 float2 (8192 floats)
    float*  sX   = dyn + 8192;             // 8192 floats  [k][row], stride 128
    float*  sA   = dyn + 8192 + 8192;      // 1024 floats

    __shared__ __align__(16) float sc[F_DIM];
    __shared__ float sCred[16][32];

    const int tid = threadIdx.x;

    // ---- Prefetch this thread's feature row ----
    const int rowL = tid >> 2;                   // 0..127
    const int q    = tid & 3;
    const int row  = blockIdx.x * MB_ROWS + rowL;
    float4 xv[8];
    {
        const float4* xr = (const float4*)(features + row * F_DIM);
#pragma unroll
        for (int i = 0; i < 8; i++) xv[i] = xr[i];
    }

    // ---- Stage params ----
    // sWBd: 4096 entries, each {w,w}. k = i>>6, col = i&63.
#pragma unroll
    for (int i = tid; i < 4096; i += 512) {
        const int k   = i >> 6;
        const int col = i & 63;
        const float w = (k < F_DIM ? W_feat[k * H_DIM + col]
                                   : b_feat[(k - F_DIM) * H_DIM + col]);
        sWBd[k * H_DIM + col] = make_float2(w, w);
    }
#pragma unroll
    for (int j = 0; j < 2; j++) {                // fold A partials (1024 floats)
        const int i = tid + j * 512;
        if (i < 1024)
            sA[i] = g_Apart[i] + g_Apart[1024 + i] + g_Apart[2048 + i] + g_Apart[3072 + i];
    }
    {                                            // fold c partials
        const int g  = tid & 31;
        const int ch = (tid >> 5) & 15;          // 0..15
        float s = 0.f;
#pragma unroll
        for (int e = 0; e < 8; e++) {
            const int ee = ch * 8 + e;           // (qq,f) flat 0..127
            s += g_Cpart[(ee >> 5) * 1024 + (ee & 31) * F_DIM + g];
        }
        sCred[ch][g] = s;
    }
    __syncthreads();
    if (tid < 32) {
        float cv = b_gate[tid];
#pragma unroll
        for (int r = 0; r < 16; r++) cv += sCred[r][tid];
        sc[tid] = cv;
    }
    __syncthreads();

    // ---- Phase 1: gates (quad: 4 threads/row, 8 logits each) ----
    float x[F_DIM];
#pragma unroll
    for (int i = 0; i < 8; i++) {
        x[4*i+0] = xv[i].x; x[4*i+1] = xv[i].y;
        x[4*i+2] = xv[i].z; x[4*i+3] = xv[i].w;
    }

    ull l2[4];
    {
        const ulonglong2* cp = (const ulonglong2*)(sc + q * 8);
        ulonglong2 ca = cp[0], cb = cp[1];
        l2[0] = ca.x; l2[1] = ca.y; l2[2] = cb.x; l2[3] = cb.y;
    }
#pragma unroll
    for (int f = 0; f < F_DIM; f++) {
        const ull xp = pk2(x[f], x[f]);
        const ulonglong2* ap = (const ulonglong2*)(sA + f * F_DIM + q * 8);
        ulonglong2 a0 = ap[0], a1 = ap[1];
        ffma2(l2[0], xp, a0.x); ffma2(l2[1], xp, a0.y);
        ffma2(l2[2], xp, a1.x); ffma2(l2[3], xp, a1.y);
    }
    float le[8];
#pragma unroll
    for (int i = 0; i < 4; i++) {
        float2 v = unpk2(l2[i]);
        le[2*i] = v.x; le[2*i+1] = v.y;
    }

    // softmax across quad
    float m = le[0];
#pragma unroll
    for (int j = 1; j < 8; j++) m = fmaxf(m, le[j]);
    m = fmaxf(m, __shfl_xor_sync(0xffffffffu, m, 1));
    m = fmaxf(m, __shfl_xor_sync(0xffffffffu, m, 2));
    float s = 0.f;
#pragma unroll
    for (int j = 0; j < 8; j++) { le[j] = __expf(le[j] - m); s += le[j]; }
    s += __shfl_xor_sync(0xffffffffu, s, 1);
    s += __shfl_xor_sync(0xffffffffu, s, 2);
    const float inv = 1.f / s;

    // write X' (k-major, stride 128)
    const int fb = q * 8;
#pragma unroll
    for (int j = 0; j < 8; j++) {
        const float gj = le[j] * inv;
        sX[(fb + j) * MB_ROWS + rowL]         = gj * x[fb + j];
        sX[(F_DIM + fb + j) * MB_ROWS + rowL] = gj;
    }
    __syncthreads();

    // ---- Phase 2: out = X' @ W', splitk2, tile 8 rows x 4 cols ----
    // Software-pipelined: k+1 loads before k's FFMA2 block.
    const int slice = tid >> 8;     // 0/1: k-half
    const int tt    = tid & 255;
    const int rg    = tt >> 4;      // 0..15 -> rows rg*8
    const int cg    = tt & 15;      // 0..15 -> cols cg*4
    const int r0    = rg * 8;
    const int c0    = cg * 4;
    const int kbase = slice * F_DIM;

    ull acc[4][4];                  // [rowpair][col]
#pragma unroll
    for (int rp = 0; rp < 4; rp++)
#pragma unroll
        for (int c2 = 0; c2 < 4; c2++) acc[rp][c2] = 0ull;

    const float*  xbase = sX + kbase * MB_ROWS + r0;
    const float2* wbase = sWBd + kbase * H_DIM + c0;

    // prologue loads (k = 0 of slice)
    ulonglong2 xa = *(const ulonglong2*)(xbase);
    ulonglong2 xb = *(const ulonglong2*)(xbase + 4);
    ulonglong2 wA = *(const ulonglong2*)(wbase);       // cols c0,c0+1 dup'd
    ulonglong2 wB = *(const ulonglong2*)(wbase + 2);   // cols c0+2,c0+3 dup'd

#pragma unroll
    for (int kk = 0; kk < F_DIM; kk++) {
        ulonglong2 xa_n, xb_n, wA_n, wB_n;
        if (kk < F_DIM - 1) {
            const float*  xp = xbase + (kk + 1) * MB_ROWS;
            const float2* wp = wbase + (kk + 1) * H_DIM;
            xa_n = *(const ulonglong2*)(xp);
            xb_n = *(const ulonglong2*)(xp + 4);
            wA_n = *(const ulonglong2*)(wp);
            wB_n = *(const ulonglong2*)(wp + 2);
        }

        ffma2(acc[0][0], xa.x, wA.x); ffma2(acc[0][1], xa.x, wA.y);
        ffma2(acc[0][2], xa.x, wB.x); ffma2(acc[0][3], xa.x, wB.y);
        ffma2(acc[1][0], xa.y, wA.x); ffma2(acc[1][1], xa.y, wA.y);
        ffma2(acc[1][2], xa.y, wB.x); ffma2(acc[1][3], xa.y, wB.y);
        ffma2(acc[2][0], xb.x, wA.x); ffma2(acc[2][1], xb.x, wA.y);
        ffma2(acc[2][2], xb.x, wB.x); ffma2(acc[2][3], xb.x, wB.y);
        ffma2(acc[3][0], xb.y, wA.x); ffma2(acc[3][1], xb.y, wA.y);
        ffma2(acc[3][2], xb.y, wB.x); ffma2(acc[3][3], xb.y, wB.y);

        if (kk < F_DIM - 1) { xa = xa_n; xb = xb_n; wA = wA_n; wB = wB_n; }
    }
    __syncthreads();   // sX reads done; reuse as splitk buffer (4096 ull = 32 KB)

    ull* red = (ull*)sX;
    if (slice == 1) {
#pragma unroll
        for (int rp = 0; rp < 4; rp++)
#pragma unroll
            for (int c2 = 0; c2 < 4; c2++)
                red[(rp * 4 + c2) * 256 + tt] = acc[rp][c2];
    }
    __syncthreads();

    if (slice == 0) {
#pragma unroll
        for (int rp = 0; rp < 4; rp++)
#pragma unroll
            for (int c2 = 0; c2 < 4; c2++)
                fadd2(acc[rp][c2], red[(rp * 4 + c2) * 256 + tt]);

        const int rowbase = blockIdx.x * MB_ROWS + r0;
#pragma unroll
        for (int rp = 0; rp < 4; rp++) {
            const float2 v0 = unpk2(acc[rp][0]);
            const float2 v1 = unpk2(acc[rp][1]);
            const float2 v2 = unpk2(acc[rp][2]);
            const float2 v3 = unpk2(acc[rp][3]);
            *(float4*)(out + (rowbase + 2 * rp) * H_DIM + c0) =
                make_float4(v0.x, v1.x, v2.x, v3.x);
            *(float4*)(out + (rowbase + 2 * rp + 1) * H_DIM + c0) =
                make_float4(v0.y, v1.y, v2.y, v3.y);
        }
    }
}

extern "C" void kernel_launch(void* const* d_in, const int* in_sizes, int n_in,
                              void* d_out, int out_size)
{
    const float* features = (const float*)d_in[0];   // [32,512,32]
    const float* W_feat   = (const float*)d_in[1];   // [32,64]
    const float* b_feat   = (const float*)d_in[2];   // [32,64]
    const float* W_gate   = (const float*)d_in[3];   // [2048,32]
    const float* b_gate   = (const float*)d_in[4];   // [32]
    float* out = (float*)d_out;                      // [32,512,64]

    const int smem_bytes = (8192 + 8192 + 1024) * 4;  // 69632
    cudaFuncSetAttribute(vsn_main_kernel,
                         cudaFuncAttributeMaxDynamicSharedMemorySize, smem_bytes);

    vsn_prep_kernel<<<128, 128>>>(W_feat, b_feat, W_gate);
    vsn_main_kernel<<<MAIN_GRID, 512, smem_bytes>>>(features, b_gate, W_feat, b_feat, out);
}

// round 17
// speedup vs baseline: 1.2138x; 1.2138x over previous
#include <cuda_runtime.h>
#include <cuda_bf16.h>

// VariableSelectionNetwork: B=32, S=512, F=32, H=64
//   A[f][g] = sum_h W_feat[f,h]*W_gate[f*H+h, g];  c = b_gate + sum b_feat.W_gate
//   gates = softmax(x @ A + c);  out = [g*x, g] @ [W_feat; b_feat]
// Prep: partial A/c over 4 h-quarters, 128 blocks.
// Main: 256 blocks x 256 threads, 64 rows/block.
//   Phase 1: quad gates (R12, proven). Phase 2: mma.sync m16n8k8 tf32 x3
//   (full fp32-grade precision), W' pre-split hi/lo in smem, X split in regs.

#define F_DIM 32
#define H_DIM 64
#define ROWS  16384
#define MB_ROWS 64
#define MAIN_GRID (ROWS / MB_ROWS)   // 256
#define ST 72                         // smem row stride (bank-conflict-free frags)

typedef unsigned long long ull;

__device__ float g_Apart[4 * 1024];
__device__ float g_Cpart[4 * 1024];

// ---------------- helpers ----------------
__device__ __forceinline__ ull pk2(float a, float b) {
    ull r; asm("mov.b64 %0, {%1, %2};" : "=l"(r) : "f"(a), "f"(b)); return r;
}
__device__ __forceinline__ void ffma2(ull& d, ull a, ull b) {
    asm("fma.rn.f32x2 %0, %1, %2, %3;" : "=l"(d) : "l"(a), "l"(b), "l"(d));
}
__device__ __forceinline__ float2 unpk2(ull v) {
    float2 r; asm("mov.b64 {%0, %1}, %2;" : "=f"(r.x), "=f"(r.y) : "l"(v)); return r;
}
__device__ __forceinline__ unsigned f2tf(float f) {
    unsigned r; asm("cvt.rna.tf32.f32 %0, %1;" : "=r"(r) : "f"(f)); return r;
}
__device__ __forceinline__ void mma8(float* d, const unsigned* a, const unsigned* b) {
    asm("mma.sync.aligned.m16n8k8.row.col.f32.tf32.tf32.f32 "
        "{%0,%1,%2,%3}, {%4,%5,%6,%7}, {%8,%9}, {%0,%1,%2,%3};"
        : "+f"(d[0]), "+f"(d[1]), "+f"(d[2]), "+f"(d[3])
        : "r"(a[0]), "r"(a[1]), "r"(a[2]), "r"(a[3]), "r"(b[0]), "r"(b[1]));
}

// ---------------------------------------------------------------------------
// Prep: 128 blocks (f = bid>>2, h-quarter q = bid&3), 128 threads.
// ---------------------------------------------------------------------------
__global__ void __launch_bounds__(128) vsn_prep_kernel(
    const float* __restrict__ W_feat,
    const float* __restrict__ b_feat,
    const float* __restrict__ W_gate)
{
    const int f  = blockIdx.x >> 2;
    const int q  = blockIdx.x & 3;
    const int g  = threadIdx.x & 31;
    const int hh = threadIdx.x >> 5;

    float a = 0.f, c = 0.f;
#pragma unroll
    for (int kk = 0; kk < 4; kk++) {
        const int h = q * 16 + hh * 4 + kk;
        const float wg = W_gate[(f * H_DIM + h) * F_DIM + g];
        a = fmaf(W_feat[f * H_DIM + h], wg, a);
        c = fmaf(b_feat[f * H_DIM + h], wg, c);
    }

    __shared__ float rA[4][32];
    __shared__ float rC[4][32];
    rA[hh][g] = a;
    rC[hh][g] = c;
    __syncthreads();

    if (threadIdx.x < 32) {
        float as = 0.f, cs = 0.f;
#pragma unroll
        for (int r = 0; r < 4; r++) { as += rA[r][threadIdx.x]; cs += rC[r][threadIdx.x]; }
        g_Apart[q * 1024 + f * F_DIM + threadIdx.x] = as;
        g_Cpart[q * 1024 + f * F_DIM + threadIdx.x] = cs;
    }
}

// ---------------------------------------------------------------------------
// Main kernel: 256 blocks x 256 threads, 64 rows/block.
// Dynamic smem: sWh[64][72]u, sWl[64][72]u, sX[64][72]f, sA[1024]f = ~58 KB.
// ---------------------------------------------------------------------------
__global__ void __launch_bounds__(256) vsn_main_kernel(
    const float* __restrict__ features,
    const float* __restrict__ b_gate,
    const float* __restrict__ W_feat,
    const float* __restrict__ b_feat,
    float* __restrict__ out)
{
    extern __shared__ float dyn[];
    unsigned* sWh = (unsigned*)dyn;            // 64*ST uints
    unsigned* sWl = (unsigned*)(dyn + 64 * ST);
    float*    sX  = dyn + 2 * 64 * ST;         // 64*ST floats
    float*    sA  = dyn + 3 * 64 * ST;         // 1024 floats

    __shared__ __align__(16) float sc[F_DIM];
    __shared__ float sCred[8][32];

    const int tid = threadIdx.x;

    // ---- Prefetch this thread's feature row ----
    const int rowL = tid >> 2;                 // 0..63
    const int q    = tid & 3;
    const int row  = blockIdx.x * MB_ROWS + rowL;
    float4 xv[8];
    {
        const float4* xr = (const float4*)(features + row * F_DIM);
#pragma unroll
        for (int i = 0; i < 8; i++) xv[i] = xr[i];
    }

    // ---- Stage W' pre-split into tf32 hi/lo bits ----
#pragma unroll
    for (int i = tid; i < 4096; i += 256) {
        const int k   = i >> 6;
        const int col = i & 63;
        const float w = (k < F_DIM ? W_feat[k * H_DIM + col]
                                   : b_feat[(k - F_DIM) * H_DIM + col]);
        const unsigned hi = f2tf(w);
        const float    lo = w - __uint_as_float(hi);
        sWh[k * ST + col] = hi;
        sWl[k * ST + col] = f2tf(lo);
    }
#pragma unroll
    for (int j = 0; j < 4; j++) {              // fold A partials
        const int i = tid + j * 256;
        sA[i] = g_Apart[i] + g_Apart[1024 + i] + g_Apart[2048 + i] + g_Apart[3072 + i];
    }
    {                                          // fold c partials
        const int g  = tid & 31;
        const int ch = tid >> 5;               // 0..7
        float s = 0.f;
#pragma unroll
        for (int e = 0; e < 16; e++) {
            const int ee = ch * 16 + e;        // (qq,f) flat 0..127
            s += g_Cpart[(ee >> 5) * 1024 + (ee & 31) * F_DIM + g];
        }
        sCred[ch][g] = s;
    }
    __syncthreads();
    if (tid < 32) {
        float cv = b_gate[tid];
#pragma unroll
        for (int r = 0; r < 8; r++) cv += sCred[r][tid];
        sc[tid] = cv;
    }
    __syncthreads();

    // ---- Phase 1: gates (quad: 4 threads/row, 8 logits each) ----
    float x[F_DIM];
#pragma unroll
    for (int i = 0; i < 8; i++) {
        x[4*i+0] = xv[i].x; x[4*i+1] = xv[i].y;
        x[4*i+2] = xv[i].z; x[4*i+3] = xv[i].w;
    }

    ull l2[4];
    {
        const ulonglong2* cp = (const ulonglong2*)(sc + q * 8);
        ulonglong2 ca = cp[0], cb = cp[1];
        l2[0] = ca.x; l2[1] = ca.y; l2[2] = cb.x; l2[3] = cb.y;
    }
#pragma unroll
    for (int f = 0; f < F_DIM; f++) {
        const ull xp = pk2(x[f], x[f]);
        const ulonglong2* ap = (const ulonglong2*)(sA + f * F_DIM + q * 8);
        ulonglong2 a0 = ap[0], a1 = ap[1];
        ffma2(l2[0], xp, a0.x); ffma2(l2[1], xp, a0.y);
        ffma2(l2[2], xp, a1.x); ffma2(l2[3], xp, a1.y);
    }
    float le[8];
#pragma unroll
    for (int i = 0; i < 4; i++) {
        float2 v = unpk2(l2[i]);
        le[2*i] = v.x; le[2*i+1] = v.y;
    }

    // softmax across quad
    float m = le[0];
#pragma unroll
    for (int j = 1; j < 8; j++) m = fmaxf(m, le[j]);
    m = fmaxf(m, __shfl_xor_sync(0xffffffffu, m, 1));
    m = fmaxf(m, __shfl_xor_sync(0xffffffffu, m, 2));
    float s = 0.f;
#pragma unroll
    for (int j = 0; j < 8; j++) { le[j] = __expf(le[j] - m); s += le[j]; }
    s += __shfl_xor_sync(0xffffffffu, s, 1);
    s += __shfl_xor_sync(0xffffffffu, s, 2);
    const float inv = 1.f / s;

    // write X' (k-major, stride ST)
    const int fb = q * 8;
#pragma unroll
    for (int j = 0; j < 8; j++) {
        const float gj = le[j] * inv;
        sX[(fb + j) * ST + rowL]         = gj * x[fb + j];
        sX[(F_DIM + fb + j) * ST + rowL] = gj;
    }
    __syncthreads();

    // ---- Phase 2: out = X' @ W' via mma.sync tf32 x3 ----
    // warp w: rows (w&3)*16..+16, n-half (w>>2)*32..+32 (4 ntiles of 8).
    const int warp = tid >> 5;
    const int lane = tid & 31;
    const int gid  = lane >> 2;     // 0..7
    const int tig  = lane & 3;      // 0..3
    const int r0   = (warp & 3) * 16;
    const int nh   = warp >> 2;     // 0/1

    // Load + split A fragments (16 rows x 64 k for this warp)
    unsigned Ah[8][4], Al[8][4];
#pragma unroll
    for (int kt = 0; kt < 8; kt++) {
        float a[4];
        a[0] = sX[(kt * 8 + tig) * ST + r0 + gid];
        a[1] = sX[(kt * 8 + tig) * ST + r0 + gid + 8];
        a[2] = sX[(kt * 8 + tig + 4) * ST + r0 + gid];
        a[3] = sX[(kt * 8 + tig + 4) * ST + r0 + gid + 8];
#pragma unroll
        for (int j = 0; j < 4; j++) {
            const unsigned hi = f2tf(a[j]);
            Ah[kt][j] = hi;
            Al[kt][j] = f2tf(a[j] - __uint_as_float(hi));
        }
    }

    float acc[4][4];
#pragma unroll
    for (int j = 0; j < 4; j++)
#pragma unroll
        for (int i = 0; i < 4; i++) acc[j][i] = 0.f;

#pragma unroll
    for (int j = 0; j < 4; j++) {              // ntile = nh*4 + j
        const int nc = (nh * 4 + j) * 8 + gid;
#pragma unroll
        for (int kt = 0; kt < 8; kt++) {
            unsigned bh[2], bl[2];
            bh[0] = sWh[(kt * 8 + tig) * ST + nc];
            bh[1] = sWh[(kt * 8 + tig + 4) * ST + nc];
            bl[0] = sWl[(kt * 8 + tig) * ST + nc];
            bl[1] = sWl[(kt * 8 + tig + 4) * ST + nc];
            mma8(acc[j], Al[kt], bh);          // lo*hi
            mma8(acc[j], Ah[kt], bl);          // hi*lo
            mma8(acc[j], Ah[kt], bh);          // hi*hi
        }
    }

    // Store: per ntile, lane covers (gid,gid+8) rows x (tig*2, tig*2+1) cols
    const int rowbase = blockIdx.x * MB_ROWS + r0;
#pragma unroll
    for (int j = 0; j < 4; j++) {
        const int col = (nh * 4 + j) * 8 + tig * 2;
        *(float2*)(out + (rowbase + gid) * H_DIM + col) =
            make_float2(acc[j][0], acc[j][1]);
        *(float2*)(out + (rowbase + gid + 8) * H_DIM + col) =
            make_float2(acc[j][2], acc[j][3]);
    }
}

extern "C" void kernel_launch(void* const* d_in, const int* in_sizes, int n_in,
                              void* d_out, int out_size)
{
    const float* features = (const float*)d_in[0];   // [32,512,32]
    const float* W_feat   = (const float*)d_in[1];   // [32,64]
    const float* b_feat   = (const float*)d_in[2];   // [32,64]
    const float* W_gate   = (const float*)d_in[3];   // [2048,32]
    const float* b_gate   = (const float*)d_in[4];   // [32]
    float* out = (float*)d_out;                      // [32,512,64]

    const int smem_bytes = (3 * 64 * ST + 1024) * 4;   // 59392
    cudaFuncSetAttribute(vsn_main_kernel,
                         cudaFuncAttributeMaxDynamicSharedMemorySize, smem_bytes);

    vsn_prep_kernel<<<128, 128>>>(W_feat, b_feat, W_gate);
    vsn_main_kernel<<<MAIN_GRID, 256, smem_bytes>>>(features, b_gate, W_feat, b_feat, out);
}